// round 7
// baseline (speedup 1.0000x reference)
#include <cuda_runtime.h>
#include <cuda_fp16.h>
#include <math.h>
#include <stdint.h>

#define E_N 64
#define H_N 512
#define F_N 2048
#define HB_STRIDE 3072   // padded token columns across all experts

// Intermediate activations, [f][padded token], zero-initialized at load.
__device__ float g_hbufT[(size_t)F_N * HB_STRIDE];  // 24 MB

__device__ __forceinline__ float gelu_exact(float v) {
    return 0.5f * v * (1.0f + erff(v * 0.70710678118654752f));
}
// Pack two fp32 into half2: lo = a, hi = b.
__device__ __forceinline__ uint32_t pack2(float a, float b) {
    uint32_t u;
    asm("cvt.rn.f16x2.f32 %0, %1, %2;" : "=r"(u) : "f"(b), "f"(a));
    return u;
}
__device__ __forceinline__ void mma16(float c[4], uint32_t a0, uint32_t a1,
                                      uint32_t a2, uint32_t a3,
                                      uint32_t b0, uint32_t b1) {
    asm volatile(
        "mma.sync.aligned.m16n8k16.row.col.f32.f16.f16.f32 "
        "{%0,%1,%2,%3},{%4,%5,%6,%7},{%8,%9},{%0,%1,%2,%3};"
        : "+f"(c[0]), "+f"(c[1]), "+f"(c[2]), "+f"(c[3])
        : "r"(a0), "r"(a1), "r"(a2), "r"(a3), "r"(b0), "r"(b1));
}
__device__ __forceinline__ void cp16(uint32_t dst, const void* src) {
    asm volatile("cp.async.cg.shared.global [%0], [%1], 16;"
                 :: "r"(dst), "l"(src) : "memory");
}
__device__ __forceinline__ void cp_commit() {
    asm volatile("cp.async.commit_group;" ::: "memory");
}
template <int N>
__device__ __forceinline__ void cp_wait() {
    asm volatile("cp.async.wait_group %0;" :: "n"(N) : "memory");
}

// ---------------------------------------------------------------------------
// A tiles (weights): fp32 in smem via cp.async, 4 slots of 16 KB.
//   PHASE 1 layout [m 128][k 32]: byte(m,k) = m*128 + ((k>>2)^(m&7))*16 + (k&3)*4
//   PHASE 2 layout [k 32][h 128]: byte(k,h) = k*512 + (((h>>2)^(k&7))*16) + (h&3)*4
// B tiles: fp16 fragment-pair layout (proven in R6), 2 buffers:
//   per (8-row n-block x 16-k kb): u32 (n, kpair p) at n*8 + (p&3)*2 + (p>>2)
//   Bs buf: [6 nb][2 kb][66 u32]
// Schedule, one __syncthreads per chunk:
//   iter c: wait_group(2); bar; stsB(c+1); ldB(c+3); cpA(c+3); commit; MMA(c)
// ---------------------------------------------------------------------------
#define A_SLOT_B 16384
#define BSZ_U32 (6 * 2 * 66)
#define SMEM_BYTES (4 * A_SLOT_B + 2 * BSZ_U32 * 4)   // 71872

template <int PHASE>
__global__ void __launch_bounds__(128)
mlp_kernel(const float* __restrict__ x, const float* __restrict__ wgt,
           const int* __restrict__ counts, float* __restrict__ outp) {
    constexpr int KTOT = (PHASE == 1) ? H_N : F_N;
    constexpr int NCH  = KTOT / 32;

    extern __shared__ __align__(16) uint8_t smem_raw[];
    uint8_t*  Ab  = smem_raw;                               // 4 fp32 A slots
    uint32_t* Bh  = (uint32_t*)(smem_raw + 4 * A_SLOT_B);   // 2 fp16 B bufs
    const uint32_t aAddr = (uint32_t)__cvta_generic_to_shared(Ab);

    const int tid = threadIdx.x;
    const int w = tid >> 5, lane = tid & 31;
    const int g = lane >> 2, tg = lane & 3;
    const int e = blockIdx.y;
    const int mbase = blockIdx.x * 128;

    // ---- in-kernel scan of tokens_per_expert (warp 0) ----
    __shared__ int s_sc[3];
    if (tid < 32) {
        const unsigned FULL = 0xffffffffu;
        int c0 = counts[lane], c1 = counts[lane + 32];
        int p0 = (c0 + 15) & ~15, p1 = (c1 + 15) & ~15;
        int i0 = c0, i1 = c1, q0 = p0, q1 = p1;
        #pragma unroll
        for (int d = 1; d < 32; d <<= 1) {
            int t;
            t = __shfl_up_sync(FULL, i0, d); if (lane >= d) i0 += t;
            t = __shfl_up_sync(FULL, i1, d); if (lane >= d) i1 += t;
            t = __shfl_up_sync(FULL, q0, d); if (lane >= d) q0 += t;
            t = __shfl_up_sync(FULL, q1, d); if (lane >= d) q1 += t;
        }
        int tot0  = __shfl_sync(FULL, i0, 31);
        int ptot0 = __shfl_sync(FULL, q0, 31);
        int el = e & 31, ex, cc, pex;
        if (e < 32) {
            ex  = __shfl_sync(FULL, i0, el) - __shfl_sync(FULL, c0, el);
            cc  = __shfl_sync(FULL, c0, el);
            pex = __shfl_sync(FULL, q0, el) - __shfl_sync(FULL, p0, el);
        } else {
            ex  = tot0 + __shfl_sync(FULL, i1, el) - __shfl_sync(FULL, c1, el);
            cc  = __shfl_sync(FULL, c1, el);
            pex = ptot0 + __shfl_sync(FULL, q1, el) - __shfl_sync(FULL, p1, el);
        }
        if (lane == 0) { s_sc[0] = ex; s_sc[1] = cc; s_sc[2] = pex; }
    }
    __syncthreads();
    const int toff = s_sc[0], cnt = s_sc[1], poff = s_sc[2];
    const float* we = wgt + (size_t)e * F_N * H_N;

    float4 rB[2][4];

    for (int tbase = 0; tbase < cnt; tbase += 48) {
        const int nlim = (cnt - tbase < 48) ? (cnt - tbase) : 48;
        const int nbl  = (nlim + 7) >> 3;

        // ---- A producer: cp.async chunk c -> slot ----
        auto cpA = [&](int slot, int c) {
            const int k0 = c * 32;
            const uint32_t sb = aAddr + slot * A_SLOT_B;
            #pragma unroll
            for (int i = 0; i < 8; ++i) {
                int q = tid + i * 128;
                if (PHASE == 1) {
                    int m = q >> 3, u = q & 7;
                    cp16(sb + m * 128 + (((u ^ (m & 7)) << 4)),
                         we + (size_t)(mbase + m) * H_N + k0 + u * 4);
                } else {
                    int k = q >> 5, u = q & 31;
                    cp16(sb + k * 512 + (((u ^ (k & 7)) << 4)),
                         we + (size_t)(k0 + k) * H_N + mbase + u * 4);
                }
            }
        };
        // ---- B producer: gmem -> regs ----
        auto ldB = [&](int set, int c) {
            const int k0 = c * 32;
            if (PHASE == 1) {
                #pragma unroll
                for (int i = 0; i < 3; ++i) {
                    int q = tid + i * 128;
                    int t = q >> 3, k4 = q & 7;
                    if (tbase + t < cnt)
                        rB[set][i] = *(const float4*)&x[(size_t)(toff + tbase + t) * H_N + k0 + k4 * 4];
                    else
                        rB[set][i] = make_float4(0.f, 0.f, 0.f, 0.f);
                }
            } else {
                #pragma unroll
                for (int i = 0; i < 2; ++i) {
                    int q = tid + i * 128;
                    if (q < 192) {
                        int n4 = q % 12, kp = q / 12;
                        const float* p0 = &g_hbufT[(size_t)(k0 + 2 * kp) * HB_STRIDE +
                                                   poff + tbase + n4 * 4];
                        rB[set][2 * i]     = *(const float4*)p0;
                        rB[set][2 * i + 1] = *(const float4*)(p0 + HB_STRIDE);
                    }
                }
            }
        };
        auto bidx = [](int n, int p) {
            int pb = p & 7;
            return ((n >> 3) * 2 + (p >> 3)) * 66 + (n & 7) * 8 + (pb & 3) * 2 + (pb >> 2);
        };
        auto stsB = [&](int buf, int set) {
            uint32_t* Bs = Bh + buf * BSZ_U32;
            if (PHASE == 1) {
                #pragma unroll
                for (int i = 0; i < 3; ++i) {
                    int q = tid + i * 128;
                    int t = q >> 3, k4 = q & 7;
                    Bs[bidx(t, 2 * k4)]     = pack2(rB[set][i].x, rB[set][i].y);
                    Bs[bidx(t, 2 * k4 + 1)] = pack2(rB[set][i].z, rB[set][i].w);
                }
            } else {
                #pragma unroll
                for (int i = 0; i < 2; ++i) {
                    int q = tid + i * 128;
                    if (q < 192) {
                        int n4 = q % 12, kp = q / 12;
                        const float* a = (const float*)&rB[set][2 * i];
                        const float* b = (const float*)&rB[set][2 * i + 1];
                        #pragma unroll
                        for (int j = 0; j < 4; ++j)
                            Bs[bidx(n4 * 4 + j, kp)] = pack2(a[j], b[j]);
                    }
                }
            }
        };

        float acc[2][6][4];
        #pragma unroll
        for (int ml = 0; ml < 2; ++ml)
            #pragma unroll
            for (int nb = 0; nb < 6; ++nb)
                #pragma unroll
                for (int r = 0; r < 4; ++r) acc[ml][nb][r] = 0.f;

        // -------- prologue --------
        ldB(0, 0); ldB(1, 1);
        stsB(0, 0);
        ldB(0, 2);
        cpA(0, 0); cp_commit();
        cpA(1, 1); cp_commit();
        cpA(2, 2); cp_commit();
        __syncthreads();

        // -------- mainloop: one barrier per chunk --------
        for (int c = 0; c < NCH; ++c) {
            cp_wait<2>();
            __syncthreads();
            if (c + 1 < NCH) stsB((c + 1) & 1, (c + 1) & 1);
            if (c + 3 < NCH) { ldB((c + 3) & 1, c + 3); cpA((c + 3) & 3, c + 3); }
            cp_commit();

            const uint8_t*  As = Ab + (c & 3) * A_SLOT_B;
            const uint32_t* Bs = Bh + (c & 1) * BSZ_U32;
            #pragma unroll
            for (int kb = 0; kb < 2; ++kb) {
                const int k = 2 * tg + 16 * kb;
                uint32_t a[2][4];
                #pragma unroll
                for (int ml = 0; ml < 2; ++ml) {
                    const int m0 = (w * 2 + ml) * 16 + g;
                    if (PHASE == 1) {
                        auto ld2 = [&](int m, int kk) -> float2 {
                            int off = m * 128 + (((kk >> 2) ^ (m & 7)) << 4) + ((kk & 3) << 2);
                            return *(const float2*)(As + off);
                        };
                        float2 v00 = ld2(m0, k),     v10 = ld2(m0 + 8, k);
                        float2 v01 = ld2(m0, k + 8), v11 = ld2(m0 + 8, k + 8);
                        a[ml][0] = pack2(v00.x, v00.y);
                        a[ml][1] = pack2(v10.x, v10.y);
                        a[ml][2] = pack2(v01.x, v01.y);
                        a[ml][3] = pack2(v11.x, v11.y);
                    } else {
                        auto ld1 = [&](int kk, int h) -> float {
                            int off = kk * 512 + ((((h >> 2) ^ (kk & 7)) << 4)) + ((h & 3) << 2);
                            return *(const float*)(As + off);
                        };
                        a[ml][0] = pack2(ld1(k, m0),     ld1(k + 1, m0));
                        a[ml][1] = pack2(ld1(k, m0 + 8), ld1(k + 1, m0 + 8));
                        a[ml][2] = pack2(ld1(k + 8, m0),     ld1(k + 9, m0));
                        a[ml][3] = pack2(ld1(k + 8, m0 + 8), ld1(k + 9, m0 + 8));
                    }
                }
                #pragma unroll
                for (int nb = 0; nb < 6; ++nb) {
                    if (nb < nbl) {
                        const uint32_t* bb = &Bs[(nb * 2 + kb) * 66];
                        uint2 pb = *(const uint2*)&bb[2 * lane];
                        mma16(acc[0][nb], a[0][0], a[0][1], a[0][2], a[0][3], pb.x, pb.y);
                        mma16(acc[1][nb], a[1][0], a[1][1], a[1][2], a[1][3], pb.x, pb.y);
                    }
                }
            }
            __syncthreads();
        }
        cp_wait<0>();

        // -------- epilogue --------
        #pragma unroll
        for (int ml = 0; ml < 2; ++ml) {
            const int r0 = mbase + (w * 2 + ml) * 16 + g;
            const int r1 = r0 + 8;
            #pragma unroll
            for (int nb = 0; nb < 6; ++nb) {
                const int n0 = nb * 8 + tg * 2;
                const float* c4 = acc[ml][nb];
                if (PHASE == 1) {
                    size_t b0 = (size_t)r0 * HB_STRIDE + poff + tbase + n0;
                    size_t b1 = (size_t)r1 * HB_STRIDE + poff + tbase + n0;
                    if (n0 + 1 < nlim) {
                        *(float2*)&g_hbufT[b0] = make_float2(gelu_exact(c4[0]), gelu_exact(c4[1]));
                        *(float2*)&g_hbufT[b1] = make_float2(gelu_exact(c4[2]), gelu_exact(c4[3]));
                    } else if (n0 < nlim) {
                        g_hbufT[b0] = gelu_exact(c4[0]);
                        g_hbufT[b1] = gelu_exact(c4[2]);
                    }
                } else {
                    const int t0 = toff + tbase + n0;
                    if (n0 < nlim) {
                        outp[(size_t)t0 * H_N + r0] = c4[0];
                        outp[(size_t)t0 * H_N + r1] = c4[2];
                    }
                    if (n0 + 1 < nlim) {
                        outp[(size_t)(t0 + 1) * H_N + r0] = c4[1];
                        outp[(size_t)(t0 + 1) * H_N + r1] = c4[3];
                    }
                }
            }
        }
        __syncthreads();  // smem reuse across token tiles
    }
}

// ---------------------------------------------------------------------------
// Inputs: d_in[0]=x [T,H] f32, d_in[1]=w1 [E,F,H] f32, d_in[2]=w2 [E,F,H] f32,
//         d_in[3]=tokens_per_expert [E] i32.  d_out=[T,H] f32.
// ---------------------------------------------------------------------------
extern "C" void kernel_launch(void* const* d_in, const int* in_sizes, int n_in,
                              void* d_out, int out_size) {
    const float* x      = (const float*)d_in[0];
    const float* w1     = (const float*)d_in[1];
    const float* w2     = (const float*)d_in[2];
    const int*   counts = (const int*)d_in[3];
    float* out = (float*)d_out;

    cudaFuncSetAttribute(mlp_kernel<1>, cudaFuncAttributeMaxDynamicSharedMemorySize, SMEM_BYTES);
    cudaFuncSetAttribute(mlp_kernel<2>, cudaFuncAttributeMaxDynamicSharedMemorySize, SMEM_BYTES);

    mlp_kernel<1><<<dim3(F_N / 128, E_N), 128, SMEM_BYTES>>>(x, w1, counts, nullptr);
    mlp_kernel<2><<<dim3(H_N / 128, E_N), 128, SMEM_BYTES>>>(x, w2, counts, out);
}